// round 13
// baseline (speedup 1.0000x reference)
#include <cuda_runtime.h>
#include <cuda_bf16.h>
#include <math.h>

// 4-qubit circuit: RY(x) encoding + 6 BasicEntangler layers -> <Z_q>.
// out_q(x) = sum_{t0,t1} g0 g1 * [ sum_{t2} g2 * (c0 + C3 c1 + S3 c2) ],
// g = (1, cos x_q, sin x_q). All-constant LDC.64 delivery (validated fastest),
// 6 samples/thread. NEW: eval is PDL-launched so its x-load + sincos prologue
// overlaps the setup kernel; cudaGridDependencySynchronize() gates the first
// coefficient read.

#define NQ 4
#define NL 6
#define NPACK 3            // 3 packs x 2 samples = 6 samples per thread
#define TPB 128

// [t012][t3 row][q*2 + dup]  (pairs duplicated for f32x2 FMA)
__constant__ __align__(16) float c_coef[27][3][8];

// ---------------------------------------------------------------------------
// f32x2 packed helpers (PTX-only on Blackwell; ptxas won't auto-fuse)
// ---------------------------------------------------------------------------
__device__ __forceinline__ unsigned long long pk2(float lo, float hi) {
    unsigned long long r;
    asm("mov.b64 %0, {%1, %2};" : "=l"(r) : "f"(lo), "f"(hi));
    return r;
}
__device__ __forceinline__ void upk2(unsigned long long v, float& lo, float& hi) {
    asm("mov.b64 {%0, %1}, %2;" : "=f"(lo), "=f"(hi) : "l"(v));
}
__device__ __forceinline__ unsigned long long mul2(unsigned long long a, unsigned long long b) {
    unsigned long long d;
    asm("mul.rn.f32x2 %0, %1, %2;" : "=l"(d) : "l"(a), "l"(b));
    return d;
}
__device__ __forceinline__ unsigned long long fma2(unsigned long long a, unsigned long long b,
                                                   unsigned long long c) {
    unsigned long long d;
    asm("fma.rn.f32x2 %0, %1, %2, %3;" : "=l"(d) : "l"(a), "l"(b), "l"(c));
    return d;
}

// ---------------------------------------------------------------------------
// Setup: simulate the 16x16 entangler unitary, build S_q = Re(U^dag Z_q U),
// factored mode-transform, write into the constant bank's backing memory.
// Layer loop ROLLED (full unroll hit the single-CTA I$ throttle in R7);
// weight loads + trig hoisted to a parallel prologue.
// ---------------------------------------------------------------------------
__global__ void setup_kernel(const float* __restrict__ w, float* __restrict__ coef_out) {
    __shared__ float sct[NL * NQ];
    __shared__ float sst[NL * NQ];
    __shared__ float Ure[16][16];
    __shared__ float Uim[16][16];
    __shared__ float Sq[1024];
    __shared__ float bufA[768];
    __shared__ float bufB[576];

    int tid = threadIdx.x;

    if (tid < NL * NQ) {
        float t = 0.5f * w[tid];
        float ct, st;
        __sincosf(t, &st, &ct);
        sct[tid] = ct;
        sst[tid] = st;
    }
    __syncthreads();

    if (tid < 16) {
        float re[16], im[16];
        #pragma unroll
        for (int b = 0; b < 16; b++) { re[b] = 0.0f; im[b] = 0.0f; }
        re[tid] = 1.0f;

        #pragma unroll 1
        for (int l = 0; l < NL; l++) {
            #pragma unroll
            for (int q = 0; q < 4; q++) {
                float ct = sct[l * 4 + q];
                float st = sst[l * 4 + q];
                int mask = 8 >> q;   // qubit 0 = MSB
                #pragma unroll
                for (int b = 0; b < 16; b++) {
                    if (b & mask) continue;
                    int p = b | mask;
                    float r0 = re[b], i0 = im[b], r1 = re[p], i1 = im[p];
                    re[b] = ct * r0 + st * i1;
                    im[b] = ct * i0 - st * r1;
                    re[p] = ct * r1 + st * i0;
                    im[p] = ct * i1 - st * r0;
                }
            }
            #pragma unroll
            for (int q = 0; q < 4; q++) {
                int cm = 8 >> q;
                int tm = 8 >> ((q + 1) & 3);
                #pragma unroll
                for (int b = 0; b < 16; b++) {
                    if (!(b & cm)) continue;
                    if (b & tm) continue;
                    int p = b | tm;
                    float tr = re[b]; re[b] = re[p]; re[p] = tr;
                    float ti = im[b]; im[b] = im[p]; im[p] = ti;
                }
            }
        }
        #pragma unroll
        for (int b = 0; b < 16; b++) { Ure[b][tid] = re[b]; Uim[b][tid] = im[b]; }
    }
    __syncthreads();

    for (int e = tid; e < 1024; e += blockDim.x) {
        int q = e >> 8;
        int i = (e >> 4) & 15;
        int j = e & 15;
        int mask = 8 >> q;
        float s = 0.0f;
        #pragma unroll
        for (int b = 0; b < 16; b++) {
            float zz = (b & mask) ? -1.0f : 1.0f;
            s += zz * (Ure[b][i] * Ure[b][j] + Uim[b][i] * Uim[b][j]);
        }
        Sq[e] = s;
    }
    __syncthreads();

    // Stage s contracts qubit-s pair index (i_s, j_s) -> t_s in basis (1, C, S):
    //   t=0: (S00+S11)/2 ; t=1: (S00-S11)/2 ; t=2: (S01+S10)/2
    const int pow3[4] = {1, 3, 9, 27};
    const float* in = Sq;
    float* out = bufA;
    for (int s = 0; s < 4; s++) {
        int R = 8 >> s;
        int T = pow3[s];
        int D = 2 * R;
        int outN = 4 * T * 3 * R * R;
        for (int e = tid; e < outN; e += blockDim.x) {
            int j2 = e % R;
            int i2 = (e / R) % R;
            int t  = (e / (R * R)) % 3;
            int tp = (e / (R * R * 3)) % T;
            int q  = e / (R * R * 3 * T);
            const float* base = in + (q * T + tp) * D * D;
            float v;
            if (t == 0)      v = 0.5f * (base[i2 * D + j2] + base[(i2 + R) * D + (j2 + R)]);
            else if (t == 1) v = 0.5f * (base[i2 * D + j2] - base[(i2 + R) * D + (j2 + R)]);
            else             v = 0.5f * (base[i2 * D + j2 + R] + base[(i2 + R) * D + j2]);
            out[(((q * T + tp) * 3 + t) * R + i2) * R + j2] = v;
        }
        __syncthreads();
        in = out;
        out = (out == bufA) ? bufB : bufA;
    }
    // in[] = [q][t], t = t0*27 + t1*9 + t2*3 + t3. Emit [t012][t3][q*2+dup].
    for (int e = tid; e < 324; e += blockDim.x) {
        int q = e / 81;
        int t = e % 81;
        int t012 = t / 3;
        int t3 = t % 3;
        float v = in[e];
        coef_out[(t012 * 3 + t3) * 8 + q * 2]     = v;
        coef_out[(t012 * 3 + t3) * 8 + q * 2 + 1] = v;
    }
}

// ---------------------------------------------------------------------------
// Eval: 6 samples per thread (3 f32x2 packs), PDL-overlapped with setup.
// Prologue (x loads + sincos + packing) runs concurrently with setup; the
// grid-dependency sync gates the first constant-bank read.
// ---------------------------------------------------------------------------
__global__ void __launch_bounds__(TPB, 3) eval_kernel(const float4* __restrict__ x,
                                                      float4* __restrict__ out,
                                                      int nB) {
    const int base = blockIdx.x * (2 * NPACK * TPB) + threadIdx.x;

    unsigned long long C0[NPACK], S0[NPACK], C1[NPACK], S1[NPACK];
    unsigned long long C2[NPACK], S2[NPACK], C3[NPACK], S3[NPACK];
    int lo[NPACK], hi[NPACK];

    #pragma unroll
    for (int p = 0; p < NPACK; p++) {
        lo[p] = base + (2 * p) * TPB;
        hi[p] = base + (2 * p + 1) * TPB;
        float4 xa = (lo[p] < nB) ? x[lo[p]] : make_float4(0.f, 0.f, 0.f, 0.f);
        float4 xb = (hi[p] < nB) ? x[hi[p]] : make_float4(0.f, 0.f, 0.f, 0.f);

        float c0a, s0a, c1a, s1a, c2a, s2a, c3a, s3a;
        float c0b, s0b, c1b, s1b, c2b, s2b, c3b, s3b;
        __sincosf(xa.x, &s0a, &c0a);  __sincosf(xb.x, &s0b, &c0b);
        __sincosf(xa.y, &s1a, &c1a);  __sincosf(xb.y, &s1b, &c1b);
        __sincosf(xa.z, &s2a, &c2a);  __sincosf(xb.z, &s2b, &c2b);
        __sincosf(xa.w, &s3a, &c3a);  __sincosf(xb.w, &s3b, &c3b);

        C0[p] = pk2(c0a, c0b);  S0[p] = pk2(s0a, s0b);
        C1[p] = pk2(c1a, c1b);  S1[p] = pk2(s1a, s1b);
        C2[p] = pk2(c2a, c2b);  S2[p] = pk2(s2a, s2b);
        C3[p] = pk2(c3a, c3b);  S3[p] = pk2(s3a, s3b);
    }

    // Wait for the producer (setup) grid before touching c_coef.
    cudaGridDependencySynchronize();

    unsigned long long acc[NPACK][4];

    #pragma unroll
    for (int t0 = 0; t0 < 3; t0++) {
        #pragma unroll
        for (int t1 = 0; t1 < 3; t1++) {
            const int a = t0 * 3 + t1;
            unsigned long long u[NPACK];
            if (a != 0) {
                #pragma unroll
                for (int p = 0; p < NPACK; p++) {
                    if (t0 == 0)      u[p] = (t1 == 1) ? C1[p] : S1[p];
                    else if (t1 == 0) u[p] = (t0 == 1) ? C0[p] : S0[p];
                    else {
                        unsigned long long e0 = (t0 == 1) ? C0[p] : S0[p];
                        unsigned long long e1 = (t1 == 1) ? C1[p] : S1[p];
                        u[p] = mul2(e0, e1);
                    }
                }
            }

            unsigned long long v2[NPACK][4];
            #pragma unroll
            for (int t2 = 0; t2 < 3; t2++) {
                const int t012 = a * 3 + t2;
                const unsigned long long* cp = (const unsigned long long*)c_coef[t012];
                #pragma unroll
                for (int p = 0; p < NPACK; p++) {
                    #pragma unroll
                    for (int q = 0; q < 4; q++) {
                        unsigned long long v3 = fma2(C3[p], cp[4 + q], cp[q]);
                        v3 = fma2(S3[p], cp[8 + q], v3);
                        if (t2 == 0)      v2[p][q] = v3;
                        else if (t2 == 1) v2[p][q] = fma2(C2[p], v3, v2[p][q]);
                        else              v2[p][q] = fma2(S2[p], v3, v2[p][q]);
                    }
                }
            }

            #pragma unroll
            for (int p = 0; p < NPACK; p++) {
                #pragma unroll
                for (int q = 0; q < 4; q++) {
                    if (a == 0) acc[p][q] = v2[p][q];
                    else        acc[p][q] = fma2(u[p], v2[p][q], acc[p][q]);
                }
            }
        }
    }

    #pragma unroll
    for (int p = 0; p < NPACK; p++) {
        float o0a, o0b, o1a, o1b, o2a, o2b, o3a, o3b;
        upk2(acc[p][0], o0a, o0b);
        upk2(acc[p][1], o1a, o1b);
        upk2(acc[p][2], o2a, o2b);
        upk2(acc[p][3], o3a, o3b);
        if (lo[p] < nB) out[lo[p]] = make_float4(o0a, o1a, o2a, o3a);
        if (hi[p] < nB) out[hi[p]] = make_float4(o0b, o1b, o2b, o3b);
    }
}

extern "C" void kernel_launch(void* const* d_in, const int* in_sizes, int n_in,
                              void* d_out, int out_size) {
    const float* x = (const float*)d_in[0];
    const float* w = (const float*)d_in[1];
    int nx = in_sizes[0];
    if (in_sizes[0] == NL * NQ && n_in > 1) {   // swapped order safety
        x = (const float*)d_in[1];
        w = (const float*)d_in[0];
        nx = in_sizes[1];
    }
    int B = nx / 4;

    void* coef_dev = nullptr;
    cudaGetSymbolAddress(&coef_dev, c_coef);

    setup_kernel<<<1, 256>>>(w, (float*)coef_dev);

    int samplesPerBlock = 2 * NPACK * TPB;   // 768
    int blocks = (B + samplesPerBlock - 1) / samplesPerBlock;

    // PDL launch: eval may start while setup runs; the in-kernel
    // cudaGridDependencySynchronize() provides the ordering.
    cudaLaunchConfig_t cfg = {};
    cfg.gridDim = dim3((unsigned)blocks);
    cfg.blockDim = dim3(TPB);
    cfg.dynamicSmemBytes = 0;
    cfg.stream = 0;
    cudaLaunchAttribute attrs[1];
    attrs[0].id = cudaLaunchAttributeProgrammaticStreamSerialization;
    attrs[0].val.programmaticStreamSerializationAllowed = 1;
    cfg.attrs = attrs;
    cfg.numAttrs = 1;
    cudaError_t err = cudaLaunchKernelEx(&cfg, eval_kernel,
                                         (const float4*)x, (float4*)d_out, B);
    if (err != cudaSuccess) {
        // Fallback: plain launch (ordering via stream serialization).
        eval_kernel<<<blocks, TPB>>>((const float4*)x, (float4*)d_out, B);
    }
}

// round 14
// speedup vs baseline: 1.0942x; 1.0942x over previous
#include <cuda_runtime.h>
#include <cuda_bf16.h>
#include <math.h>

// 4-qubit circuit: RY(x) encoding + 6 BasicEntangler layers -> <Z_q>.
// out_q(x) = sum_{t0,t1} g0 g1 * [ sum_{t2} g2 * (c0 + C3 c1 + S3 c2) ],
// g = (1, cos x_q, sin x_q). All-constant LDC.64 delivery, 6 samples/thread.
// PDL: setup triggers launch-completion IMMEDIATELY (first statement), so
// eval's x-load + sincos prologue overlaps the whole setup kernel; the
// consumer-side cudaGridDependencySynchronize() gates the first LDC.

#define NQ 4
#define NL 6
#define NPACK 3            // 3 packs x 2 samples = 6 samples per thread
#define TPB 128

// [t012][t3 row][q*2 + dup]  (pairs duplicated for f32x2 FMA)
__constant__ __align__(16) float c_coef[27][3][8];

// ---------------------------------------------------------------------------
// f32x2 packed helpers (PTX-only on Blackwell; ptxas won't auto-fuse)
// ---------------------------------------------------------------------------
__device__ __forceinline__ unsigned long long pk2(float lo, float hi) {
    unsigned long long r;
    asm("mov.b64 %0, {%1, %2};" : "=l"(r) : "f"(lo), "f"(hi));
    return r;
}
__device__ __forceinline__ void upk2(unsigned long long v, float& lo, float& hi) {
    asm("mov.b64 {%0, %1}, %2;" : "=f"(lo), "=f"(hi) : "l"(v));
}
__device__ __forceinline__ unsigned long long mul2(unsigned long long a, unsigned long long b) {
    unsigned long long d;
    asm("mul.rn.f32x2 %0, %1, %2;" : "=l"(d) : "l"(a), "l"(b));
    return d;
}
__device__ __forceinline__ unsigned long long fma2(unsigned long long a, unsigned long long b,
                                                   unsigned long long c) {
    unsigned long long d;
    asm("fma.rn.f32x2 %0, %1, %2, %3;" : "=l"(d) : "l"(a), "l"(b), "l"(c));
    return d;
}

// ---------------------------------------------------------------------------
// Setup: simulate the 16x16 entangler unitary, build S_q = Re(U^dag Z_q U),
// factored mode-transform, write into the constant bank's backing memory.
// Fires the PDL trigger FIRST so the eval grid can launch and run its
// coefficient-independent prologue concurrently.
// ---------------------------------------------------------------------------
__global__ void setup_kernel(const float* __restrict__ w, float* __restrict__ coef_out) {
    // Allow the dependent eval grid to launch right away.
    cudaTriggerProgrammaticLaunchCompletion();

    __shared__ float sct[NL * NQ];
    __shared__ float sst[NL * NQ];
    __shared__ float Ure[16][16];
    __shared__ float Uim[16][16];
    __shared__ float Sq[1024];
    __shared__ float bufA[768];
    __shared__ float bufB[576];

    int tid = threadIdx.x;

    if (tid < NL * NQ) {
        float t = 0.5f * w[tid];
        float ct, st;
        __sincosf(t, &st, &ct);
        sct[tid] = ct;
        sst[tid] = st;
    }
    __syncthreads();

    if (tid < 16) {
        float re[16], im[16];
        #pragma unroll
        for (int b = 0; b < 16; b++) { re[b] = 0.0f; im[b] = 0.0f; }
        re[tid] = 1.0f;

        #pragma unroll 1
        for (int l = 0; l < NL; l++) {
            #pragma unroll
            for (int q = 0; q < 4; q++) {
                float ct = sct[l * 4 + q];
                float st = sst[l * 4 + q];
                int mask = 8 >> q;   // qubit 0 = MSB
                #pragma unroll
                for (int b = 0; b < 16; b++) {
                    if (b & mask) continue;
                    int p = b | mask;
                    float r0 = re[b], i0 = im[b], r1 = re[p], i1 = im[p];
                    re[b] = ct * r0 + st * i1;
                    im[b] = ct * i0 - st * r1;
                    re[p] = ct * r1 + st * i0;
                    im[p] = ct * i1 - st * r0;
                }
            }
            #pragma unroll
            for (int q = 0; q < 4; q++) {
                int cm = 8 >> q;
                int tm = 8 >> ((q + 1) & 3);
                #pragma unroll
                for (int b = 0; b < 16; b++) {
                    if (!(b & cm)) continue;
                    if (b & tm) continue;
                    int p = b | tm;
                    float tr = re[b]; re[b] = re[p]; re[p] = tr;
                    float ti = im[b]; im[b] = im[p]; im[p] = ti;
                }
            }
        }
        #pragma unroll
        for (int b = 0; b < 16; b++) { Ure[b][tid] = re[b]; Uim[b][tid] = im[b]; }
    }
    __syncthreads();

    for (int e = tid; e < 1024; e += blockDim.x) {
        int q = e >> 8;
        int i = (e >> 4) & 15;
        int j = e & 15;
        int mask = 8 >> q;
        float s = 0.0f;
        #pragma unroll
        for (int b = 0; b < 16; b++) {
            float zz = (b & mask) ? -1.0f : 1.0f;
            s += zz * (Ure[b][i] * Ure[b][j] + Uim[b][i] * Uim[b][j]);
        }
        Sq[e] = s;
    }
    __syncthreads();

    // Stage s contracts qubit-s pair index (i_s, j_s) -> t_s in basis (1, C, S):
    //   t=0: (S00+S11)/2 ; t=1: (S00-S11)/2 ; t=2: (S01+S10)/2
    const int pow3[4] = {1, 3, 9, 27};
    const float* in = Sq;
    float* out = bufA;
    for (int s = 0; s < 4; s++) {
        int R = 8 >> s;
        int T = pow3[s];
        int D = 2 * R;
        int outN = 4 * T * 3 * R * R;
        for (int e = tid; e < outN; e += blockDim.x) {
            int j2 = e % R;
            int i2 = (e / R) % R;
            int t  = (e / (R * R)) % 3;
            int tp = (e / (R * R * 3)) % T;
            int q  = e / (R * R * 3 * T);
            const float* base = in + (q * T + tp) * D * D;
            float v;
            if (t == 0)      v = 0.5f * (base[i2 * D + j2] + base[(i2 + R) * D + (j2 + R)]);
            else if (t == 1) v = 0.5f * (base[i2 * D + j2] - base[(i2 + R) * D + (j2 + R)]);
            else             v = 0.5f * (base[i2 * D + j2 + R] + base[(i2 + R) * D + j2]);
            out[(((q * T + tp) * 3 + t) * R + i2) * R + j2] = v;
        }
        __syncthreads();
        in = out;
        out = (out == bufA) ? bufB : bufA;
    }
    // in[] = [q][t], t = t0*27 + t1*9 + t2*3 + t3. Emit [t012][t3][q*2+dup].
    for (int e = tid; e < 324; e += blockDim.x) {
        int q = e / 81;
        int t = e % 81;
        int t012 = t / 3;
        int t3 = t % 3;
        float v = in[e];
        coef_out[(t012 * 3 + t3) * 8 + q * 2]     = v;
        coef_out[(t012 * 3 + t3) * 8 + q * 2 + 1] = v;
    }
}

// ---------------------------------------------------------------------------
// Eval: 6 samples per thread (3 f32x2 packs), PDL-overlapped with setup.
// Prologue (x loads + sincos + packing) runs concurrently with setup; the
// grid-dependency sync gates the first constant-bank read.
// ---------------------------------------------------------------------------
__global__ void __launch_bounds__(TPB, 3) eval_kernel(const float4* __restrict__ x,
                                                      float4* __restrict__ out,
                                                      int nB) {
    const int base = blockIdx.x * (2 * NPACK * TPB) + threadIdx.x;

    unsigned long long C0[NPACK], S0[NPACK], C1[NPACK], S1[NPACK];
    unsigned long long C2[NPACK], S2[NPACK], C3[NPACK], S3[NPACK];
    int lo[NPACK], hi[NPACK];

    #pragma unroll
    for (int p = 0; p < NPACK; p++) {
        lo[p] = base + (2 * p) * TPB;
        hi[p] = base + (2 * p + 1) * TPB;
        float4 xa = (lo[p] < nB) ? x[lo[p]] : make_float4(0.f, 0.f, 0.f, 0.f);
        float4 xb = (hi[p] < nB) ? x[hi[p]] : make_float4(0.f, 0.f, 0.f, 0.f);

        float c0a, s0a, c1a, s1a, c2a, s2a, c3a, s3a;
        float c0b, s0b, c1b, s1b, c2b, s2b, c3b, s3b;
        __sincosf(xa.x, &s0a, &c0a);  __sincosf(xb.x, &s0b, &c0b);
        __sincosf(xa.y, &s1a, &c1a);  __sincosf(xb.y, &s1b, &c1b);
        __sincosf(xa.z, &s2a, &c2a);  __sincosf(xb.z, &s2b, &c2b);
        __sincosf(xa.w, &s3a, &c3a);  __sincosf(xb.w, &s3b, &c3b);

        C0[p] = pk2(c0a, c0b);  S0[p] = pk2(s0a, s0b);
        C1[p] = pk2(c1a, c1b);  S1[p] = pk2(s1a, s1b);
        C2[p] = pk2(c2a, c2b);  S2[p] = pk2(s2a, s2b);
        C3[p] = pk2(c3a, c3b);  S3[p] = pk2(s3a, s3b);
    }

    // Wait for the producer (setup) grid's writes before touching c_coef.
    cudaGridDependencySynchronize();

    unsigned long long acc[NPACK][4];

    #pragma unroll
    for (int t0 = 0; t0 < 3; t0++) {
        #pragma unroll
        for (int t1 = 0; t1 < 3; t1++) {
            const int a = t0 * 3 + t1;
            unsigned long long u[NPACK];
            if (a != 0) {
                #pragma unroll
                for (int p = 0; p < NPACK; p++) {
                    if (t0 == 0)      u[p] = (t1 == 1) ? C1[p] : S1[p];
                    else if (t1 == 0) u[p] = (t0 == 1) ? C0[p] : S0[p];
                    else {
                        unsigned long long e0 = (t0 == 1) ? C0[p] : S0[p];
                        unsigned long long e1 = (t1 == 1) ? C1[p] : S1[p];
                        u[p] = mul2(e0, e1);
                    }
                }
            }

            unsigned long long v2[NPACK][4];
            #pragma unroll
            for (int t2 = 0; t2 < 3; t2++) {
                const int t012 = a * 3 + t2;
                const unsigned long long* cp = (const unsigned long long*)c_coef[t012];
                #pragma unroll
                for (int p = 0; p < NPACK; p++) {
                    #pragma unroll
                    for (int q = 0; q < 4; q++) {
                        unsigned long long v3 = fma2(C3[p], cp[4 + q], cp[q]);
                        v3 = fma2(S3[p], cp[8 + q], v3);
                        if (t2 == 0)      v2[p][q] = v3;
                        else if (t2 == 1) v2[p][q] = fma2(C2[p], v3, v2[p][q]);
                        else              v2[p][q] = fma2(S2[p], v3, v2[p][q]);
                    }
                }
            }

            #pragma unroll
            for (int p = 0; p < NPACK; p++) {
                #pragma unroll
                for (int q = 0; q < 4; q++) {
                    if (a == 0) acc[p][q] = v2[p][q];
                    else        acc[p][q] = fma2(u[p], v2[p][q], acc[p][q]);
                }
            }
        }
    }

    #pragma unroll
    for (int p = 0; p < NPACK; p++) {
        float o0a, o0b, o1a, o1b, o2a, o2b, o3a, o3b;
        upk2(acc[p][0], o0a, o0b);
        upk2(acc[p][1], o1a, o1b);
        upk2(acc[p][2], o2a, o2b);
        upk2(acc[p][3], o3a, o3b);
        if (lo[p] < nB) out[lo[p]] = make_float4(o0a, o1a, o2a, o3a);
        if (hi[p] < nB) out[hi[p]] = make_float4(o0b, o1b, o2b, o3b);
    }
}

extern "C" void kernel_launch(void* const* d_in, const int* in_sizes, int n_in,
                              void* d_out, int out_size) {
    const float* x = (const float*)d_in[0];
    const float* w = (const float*)d_in[1];
    int nx = in_sizes[0];
    if (in_sizes[0] == NL * NQ && n_in > 1) {   // swapped order safety
        x = (const float*)d_in[1];
        w = (const float*)d_in[0];
        nx = in_sizes[1];
    }
    int B = nx / 4;

    void* coef_dev = nullptr;
    cudaGetSymbolAddress(&coef_dev, c_coef);

    setup_kernel<<<1, 256>>>(w, (float*)coef_dev);

    int samplesPerBlock = 2 * NPACK * TPB;   // 768
    int blocks = (B + samplesPerBlock - 1) / samplesPerBlock;

    // PDL launch: eval may start while setup runs (setup triggers at entry);
    // the in-kernel cudaGridDependencySynchronize() provides the ordering.
    cudaLaunchConfig_t cfg = {};
    cfg.gridDim = dim3((unsigned)blocks);
    cfg.blockDim = dim3(TPB);
    cfg.dynamicSmemBytes = 0;
    cfg.stream = 0;
    cudaLaunchAttribute attrs[1];
    attrs[0].id = cudaLaunchAttributeProgrammaticStreamSerialization;
    attrs[0].val.programmaticStreamSerializationAllowed = 1;
    cfg.attrs = attrs;
    cfg.numAttrs = 1;
    cudaError_t err = cudaLaunchKernelEx(&cfg, eval_kernel,
                                         (const float4*)x, (float4*)d_out, B);
    if (err != cudaSuccess) {
        // Fallback: plain launch (ordering via stream serialization).
        eval_kernel<<<blocks, TPB>>>((const float4*)x, (float4*)d_out, B);
    }
}